// round 9
// baseline (speedup 1.0000x reference)
#include <cuda_runtime.h>
#include <cuda_bf16.h>
#include <cstdint>

#define NN 100000
#define EE 1600000
#define DD 128
#define NB 98            // ceil(NN/1024)

// ---------------- scratch (device globals: no allocation allowed) ----------------
__device__ int   g_counts[NN];
__device__ int   g_offsets[NN];
__device__ int   g_fill[NN];
__device__ float g_deginv[NN];
__device__ int   g_bsums[128];
__device__ int   g_csr_src[EE];
__device__ float g_mean[(size_t)NN * DD];
__device__ float g_h[(size_t)NN * DD];
// preconverted weights hi/lo: [layer][256][128] (rows 0-127 = Wself, 128-255 = Wneigh)
__device__ __nv_bfloat16 g_whi[2 * 256 * DD];
__device__ __nv_bfloat16 g_wlo[2 * 256 * DD];

// ---------------- CSR build ----------------
__global__ void hist_kernel(const int* __restrict__ dst) {
    int i = blockIdx.x * blockDim.x + threadIdx.x;
    if (i < EE) atomicAdd(&g_counts[dst[i]], 1);
}

__global__ void scan_local_kernel() {
    __shared__ int wsums[32];
    int tid = threadIdx.x, lane = tid & 31, warp = tid >> 5;
    int i = blockIdx.x * 1024 + tid;
    int v = (i < NN) ? g_counts[i] : 0;
    int x = v;
    #pragma unroll
    for (int o = 1; o < 32; o <<= 1) {
        int t = __shfl_up_sync(0xffffffffu, x, o);
        if (lane >= o) x += t;
    }
    if (lane == 31) wsums[warp] = x;
    __syncthreads();
    if (warp == 0) {
        int w = wsums[lane];
        #pragma unroll
        for (int o = 1; o < 32; o <<= 1) {
            int t = __shfl_up_sync(0xffffffffu, w, o);
            if (lane >= o) w += t;
        }
        wsums[lane] = w;
    }
    __syncthreads();
    int incl = x + (warp ? wsums[warp - 1] : 0);
    if (i < NN) g_offsets[i] = incl - v;               // block-local exclusive
    if (tid == 1023) g_bsums[blockIdx.x] = incl;       // block total
}

// finalize with fused block-sums scan (each block redundantly scans the 98 sums)
__global__ void finalize_kernel() {
    __shared__ int pref[NB];
    int tid = threadIdx.x;
    if (tid < NB) pref[tid] = g_bsums[tid];
    __syncthreads();
    if (tid == 0) {
        int run = 0;
        #pragma unroll 7
        for (int j = 0; j < NB; ++j) { int t = pref[j]; pref[j] = run; run += t; }
    }
    __syncthreads();
    int i = blockIdx.x * blockDim.x + tid;
    if (i < NN) {
        int off = g_offsets[i] + pref[i >> 10];
        g_offsets[i] = off;
        g_fill[i]    = off;
        int c = g_counts[i];
        g_deginv[i]  = 1.0f / (float)((c > 1) ? c : 1);
    }
}

// scatter + fused weight hi/lo preconversion (extra 64 blocks)
#define SC_BLOCKS ((EE + 255) / 256)
__global__ void scatter_fused_kernel(const int* __restrict__ src, const int* __restrict__ dst,
                                     const float* __restrict__ W1s, const float* __restrict__ W1n,
                                     const float* __restrict__ W2s, const float* __restrict__ W2n) {
    if (blockIdx.x < SC_BLOCKS) {
        int i = blockIdx.x * 256 + threadIdx.x;
        if (i < EE) {
            int d = dst[i];
            int p = atomicAdd(&g_fill[d], 1);
            g_csr_src[p] = src[i];
        }
    } else {
        int i = (blockIdx.x - SC_BLOCKS) * 256 + threadIdx.x;  // float4 index, 16384 total
        if (i >= 16384) return;
        int layer = i >> 13;
        int r256  = (i >> 5) & 255;
        int c4    = i & 31;
        const float* Wsrc = (layer == 0)
            ? ((r256 < 128) ? W1s + (size_t)r256 * DD : W1n + (size_t)(r256 - 128) * DD)
            : ((r256 < 128) ? W2s + (size_t)r256 * DD : W2n + (size_t)(r256 - 128) * DD);
        float4 v = *reinterpret_cast<const float4*>(Wsrc + c4 * 4);
        float hx = __bfloat162float(__float2bfloat16_rn(v.x));
        float hy = __bfloat162float(__float2bfloat16_rn(v.y));
        float hz = __bfloat162float(__float2bfloat16_rn(v.z));
        float hw = __bfloat162float(__float2bfloat16_rn(v.w));
        __nv_bfloat162 h0 = __floats2bfloat162_rn(v.x, v.y);
        __nv_bfloat162 h1 = __floats2bfloat162_rn(v.z, v.w);
        __nv_bfloat162 l0 = __floats2bfloat162_rn(v.x - hx, v.y - hy);
        __nv_bfloat162 l1 = __floats2bfloat162_rn(v.z - hz, v.w - hw);
        reinterpret_cast<uint2*>(g_whi)[i] = make_uint2(*(uint32_t*)&h0, *(uint32_t*)&h1);
        reinterpret_cast<uint2*>(g_wlo)[i] = make_uint2(*(uint32_t*)&l0, *(uint32_t*)&l1);
    }
}

// ---- mean aggregation: warp/node, edge-unroll x8, next-group index prefetch ----
__global__ void agg_kernel(const float* __restrict__ x, float* __restrict__ outmean) {
    int node = (blockIdx.x * blockDim.x + threadIdx.x) >> 5;
    int lane = threadIdx.x & 31;
    if (node >= NN) return;
    int s   = g_offsets[node];
    int cnt = g_counts[node];
    float a0 = 0.f, a1 = 0.f, a2 = 0.f, a3 = 0.f;
    int ngroups = cnt >> 3;
    int idx[8];
    if (ngroups > 0) {
        #pragma unroll
        for (int u = 0; u < 8; ++u) idx[u] = __ldg(&g_csr_src[s + u]);
    }
    for (int g = 0; g < ngroups; ++g) {
        int cur[8];
        #pragma unroll
        for (int u = 0; u < 8; ++u) cur[u] = idx[u];
        if (g + 1 < ngroups) {                   // prefetch next group's indices
            int sn = s + (g + 1) * 8;
            #pragma unroll
            for (int u = 0; u < 8; ++u) idx[u] = __ldg(&g_csr_src[sn + u]);
        }
        float4 v[8];
        #pragma unroll
        for (int u = 0; u < 8; ++u)
            v[u] = __ldg(reinterpret_cast<const float4*>(x + (size_t)cur[u] * DD + lane * 4));
        #pragma unroll
        for (int u = 0; u < 8; ++u) {
            a0 += v[u].x; a1 += v[u].y; a2 += v[u].z; a3 += v[u].w;
        }
    }
    for (int t = ngroups << 3; t < cnt; ++t) {
        int i0 = __ldg(&g_csr_src[s + t]);
        float4 v = __ldg(reinterpret_cast<const float4*>(x + (size_t)i0 * DD + lane * 4));
        a0 += v.x; a1 += v.y; a2 += v.z; a3 += v.w;
    }
    float di = g_deginv[node];
    float4 o = make_float4(a0 * di, a1 * di, a2 * di, a3 * di);
    *reinterpret_cast<float4*>(outmean + (size_t)node * DD + lane * 4) = o;
}

// ====== tensor-core GEMM: double-buffered smem + register-prefetched A ======
__device__ __forceinline__ uint32_t smem_u32(const void* p) {
    uint32_t a;
    asm("{ .reg .u64 t; cvta.to.shared.u64 t, %1; cvt.u32.u64 %0, t; }" : "=r"(a) : "l"(p));
    return a;
}
__device__ __forceinline__ void ldsm_x4(uint32_t& r0, uint32_t& r1, uint32_t& r2, uint32_t& r3, uint32_t a) {
    asm volatile("ldmatrix.sync.aligned.m8n8.x4.shared.b16 {%0,%1,%2,%3}, [%4];"
                 : "=r"(r0), "=r"(r1), "=r"(r2), "=r"(r3) : "r"(a));
}
__device__ __forceinline__ void ldsm_x4_t(uint32_t& r0, uint32_t& r1, uint32_t& r2, uint32_t& r3, uint32_t a) {
    asm volatile("ldmatrix.sync.aligned.m8n8.x4.trans.shared.b16 {%0,%1,%2,%3}, [%4];"
                 : "=r"(r0), "=r"(r1), "=r"(r2), "=r"(r3) : "r"(a));
}
__device__ __forceinline__ void mma_bf16(float* c, uint32_t a0, uint32_t a1, uint32_t a2, uint32_t a3,
                                         uint32_t b0, uint32_t b1) {
    asm volatile("mma.sync.aligned.m16n8k16.row.col.f32.bf16.bf16.f32 "
                 "{%0,%1,%2,%3}, {%4,%5,%6,%7}, {%8,%9}, {%0,%1,%2,%3};"
                 : "+f"(c[0]), "+f"(c[1]), "+f"(c[2]), "+f"(c[3])
                 : "r"(a0), "r"(a1), "r"(a2), "r"(a3), "r"(b0), "r"(b1));
}
__device__ __forceinline__ uint32_t pack_bf2(float x, float y) {
    __nv_bfloat162 t = __floats2bfloat162_rn(x, y);
    return *reinterpret_cast<uint32_t*>(&t);
}

#define APAD 40
#define BPAD 136
// byte offsets within one buffer
#define OFF_AH 0
#define OFF_AL 10240
#define OFF_BH 20480
#define OFF_BL 29184
#define BUFSZ  37888
#define GSMEM  (2 * BUFSZ)

__global__ __launch_bounds__(256, 2) void gemm_mma_kernel(
    const float* __restrict__ A1, const float* __restrict__ A2,
    const __nv_bfloat16* __restrict__ Wh, const __nv_bfloat16* __restrict__ Wl,
    const float* __restrict__ bias, float* __restrict__ out, int relu)
{
    extern __shared__ char smem[];
    int tid = threadIdx.x, lane = tid & 31, wid = tid >> 5;
    int warp_m = wid & 3;
    int warp_n = wid >> 2;
    int m0 = blockIdx.x * 128;
    uint32_t sb = smem_u32(smem);

    float acc[2][8][4];
    #pragma unroll
    for (int i = 0; i < 2; ++i)
        #pragma unroll
        for (int j = 0; j < 8; ++j)
            #pragma unroll
            for (int q = 0; q < 4; ++q) acc[i][j][q] = 0.f;

    int a_lrow = lane & 15;
    int a_lcol = (lane >> 4) << 3;
    int b_lk   = lane & 15;
    int b_ln   = (lane >> 4) << 3;

    float4 av[4];
    // ---- prologue: load + store chunk 0 into buffer 0 ----
    #pragma unroll
    for (int i = 0; i < 4; ++i) {
        int f = tid + i * 256;
        int row = f >> 3, c4 = (f & 7) * 4;
        int gm = m0 + row;
        av[i] = (gm < NN) ? __ldg(reinterpret_cast<const float4*>(A1 + (size_t)gm * DD + c4))
                          : make_float4(0.f, 0.f, 0.f, 0.f);
    }
    {
        char* base = smem;   // buffer 0
        #pragma unroll
        for (int i = 0; i < 4; ++i) {
            int f = tid + i * 256;
            int row = f >> 3, c4 = (f & 7) * 4;
            float4 v = av[i];
            float hx = __bfloat162float(__float2bfloat16_rn(v.x));
            float hy = __bfloat162float(__float2bfloat16_rn(v.y));
            float hz = __bfloat162float(__float2bfloat16_rn(v.z));
            float hw = __bfloat162float(__float2bfloat16_rn(v.w));
            uint32_t off = (uint32_t)(row * APAD + c4) * 2;
            uint32_t* ph = reinterpret_cast<uint32_t*>(base + OFF_AH + off);
            ph[0] = pack_bf2(v.x, v.y); ph[1] = pack_bf2(v.z, v.w);
            uint32_t* pl = reinterpret_cast<uint32_t*>(base + OFF_AL + off);
            pl[0] = pack_bf2(v.x - hx, v.y - hy); pl[1] = pack_bf2(v.z - hz, v.w - hw);
        }
        #pragma unroll
        for (int i = 0; i < 4; ++i) {
            int u = tid + i * 256;
            int bufb = u >> 9, kr = (u >> 4) & 31, n8 = (u & 15) * 8;
            const __nv_bfloat16* s = bufb ? Wl : Wh;
            uint4 v = __ldg(reinterpret_cast<const uint4*>(s + (size_t)kr * DD + n8));
            *reinterpret_cast<uint4*>(base + (bufb ? OFF_BL : OFF_BH) + (uint32_t)(kr * BPAD + n8) * 2) = v;
        }
    }
    __syncthreads();

    for (int ch = 0; ch < 8; ++ch) {
        // ---- prefetch next chunk's A into registers (latency hides under MMA) ----
        float4 av2[4];
        if (ch < 7) {
            const float* Abase = (ch + 1 < 4) ? A1 : A2;
            int cb = ((ch + 1) & 3) * 32;
            #pragma unroll
            for (int i = 0; i < 4; ++i) {
                int f = tid + i * 256;
                int row = f >> 3, c4 = (f & 7) * 4;
                int gm = m0 + row;
                av2[i] = (gm < NN) ? __ldg(reinterpret_cast<const float4*>(Abase + (size_t)gm * DD + cb + c4))
                                   : make_float4(0.f, 0.f, 0.f, 0.f);
            }
        }

        // ---- compute from buffer ch&1 ----
        uint32_t bufbase = sb + (uint32_t)(ch & 1) * BUFSZ;
        uint32_t ah_b = bufbase + OFF_AH;
        uint32_t al_b = bufbase + OFF_AL;
        uint32_t bh_b = bufbase + OFF_BH;
        uint32_t bl_b = bufbase + OFF_BL;

        #pragma unroll
        for (int p = 0; p < 3; ++p) {
            uint32_t ab = (p == 1) ? al_b : ah_b;
            uint32_t bb = (p == 2) ? bl_b : bh_b;
            #pragma unroll
            for (int ks = 0; ks < 2; ++ks) {
                uint32_t a[2][4];
                #pragma unroll
                for (int mt = 0; mt < 2; ++mt) {
                    int row = warp_m * 32 + mt * 16 + a_lrow;
                    int col = ks * 16 + a_lcol;
                    ldsm_x4(a[mt][0], a[mt][1], a[mt][2], a[mt][3],
                            ab + (uint32_t)(row * APAD + col) * 2);
                }
                #pragma unroll
                for (int ng = 0; ng < 4; ++ng) {
                    int kk = ks * 16 + b_lk;
                    int nn = warp_n * 64 + ng * 16 + b_ln;
                    uint32_t b0, b1, b2, b3;
                    ldsm_x4_t(b0, b1, b2, b3, bb + (uint32_t)(kk * BPAD + nn) * 2);
                    #pragma unroll
                    for (int mt = 0; mt < 2; ++mt) {
                        mma_bf16(acc[mt][ng * 2 + 0], a[mt][0], a[mt][1], a[mt][2], a[mt][3], b0, b1);
                        mma_bf16(acc[mt][ng * 2 + 1], a[mt][0], a[mt][1], a[mt][2], a[mt][3], b2, b3);
                    }
                }
            }
        }

        // ---- convert + store next chunk into other buffer ----
        if (ch < 7) {
            char* base = smem + ((ch + 1) & 1) * BUFSZ;
            #pragma unroll
            for (int i = 0; i < 4; ++i) {
                int f = tid + i * 256;
                int row = f >> 3, c4 = (f & 7) * 4;
                float4 v = av2[i];
                float hx = __bfloat162float(__float2bfloat16_rn(v.x));
                float hy = __bfloat162float(__float2bfloat16_rn(v.y));
                float hz = __bfloat162float(__float2bfloat16_rn(v.z));
                float hw = __bfloat162float(__float2bfloat16_rn(v.w));
                uint32_t off = (uint32_t)(row * APAD + c4) * 2;
                uint32_t* ph = reinterpret_cast<uint32_t*>(base + OFF_AH + off);
                ph[0] = pack_bf2(v.x, v.y); ph[1] = pack_bf2(v.z, v.w);
                uint32_t* pl = reinterpret_cast<uint32_t*>(base + OFF_AL + off);
                pl[0] = pack_bf2(v.x - hx, v.y - hy); pl[1] = pack_bf2(v.z - hz, v.w - hw);
            }
            #pragma unroll
            for (int i = 0; i < 4; ++i) {
                int u = tid + i * 256;
                int bufb = u >> 9, kr = (u >> 4) & 31, n8 = (u & 15) * 8;
                const __nv_bfloat16* s = bufb ? Wl : Wh;
                uint4 v = __ldg(reinterpret_cast<const uint4*>(s + (size_t)((ch + 1) * 32 + kr) * DD + n8));
                *reinterpret_cast<uint4*>(base + (bufb ? OFF_BL : OFF_BH) + (uint32_t)(kr * BPAD + n8) * 2) = v;
            }
            __syncthreads();
        }
    }

    // --- epilogue ---
    int crow = lane >> 2;
    int ccol = (lane & 3) * 2;
    #pragma unroll
    for (int mt = 0; mt < 2; ++mt) {
        #pragma unroll
        for (int nt = 0; nt < 8; ++nt) {
            int col = warp_n * 64 + nt * 8 + ccol;
            float2 bb = __ldg(reinterpret_cast<const float2*>(bias + col));
            #pragma unroll
            for (int h = 0; h < 2; ++h) {
                int row = m0 + warp_m * 32 + mt * 16 + crow + h * 8;
                if (row >= NN) continue;
                float lo = acc[mt][nt][h * 2 + 0] + bb.x;
                float hi = acc[mt][nt][h * 2 + 1] + bb.y;
                if (relu) { lo = fmaxf(lo, 0.f); hi = fmaxf(hi, 0.f); }
                *reinterpret_cast<float2*>(out + (size_t)row * DD + col) = make_float2(lo, hi);
            }
        }
    }
}

// ---------------- launch ----------------
extern "C" void kernel_launch(void* const* d_in, const int* in_sizes, int n_in,
                              void* d_out, int out_size) {
    const float* in_feat  = (const float*)d_in[0];
    const float* W1_self  = (const float*)d_in[1];
    const float* W1_neigh = (const float*)d_in[2];
    const float* b1       = (const float*)d_in[3];
    const float* W2_self  = (const float*)d_in[4];
    const float* W2_neigh = (const float*)d_in[5];
    const float* b2       = (const float*)d_in[6];
    const int*   src      = (const int*)d_in[7];
    const int*   dst      = (const int*)d_in[8];
    float* out = (float*)d_out;

    int* counts_p;
    float *mean_p, *h_p;
    __nv_bfloat16 *whi_p, *wlo_p;
    cudaGetSymbolAddress((void**)&counts_p, g_counts);
    cudaGetSymbolAddress((void**)&mean_p, g_mean);
    cudaGetSymbolAddress((void**)&h_p, g_h);
    cudaGetSymbolAddress((void**)&whi_p, g_whi);
    cudaGetSymbolAddress((void**)&wlo_p, g_wlo);

    cudaFuncSetAttribute(gemm_mma_kernel, cudaFuncAttributeMaxDynamicSharedMemorySize, GSMEM);

    cudaMemsetAsync(counts_p, 0, NN * sizeof(int));

    hist_kernel<<<(EE + 255) / 256, 256>>>(dst);
    scan_local_kernel<<<NB, 1024>>>();
    finalize_kernel<<<(NN + 255) / 256, 256>>>();
    scatter_fused_kernel<<<SC_BLOCKS + 64, 256>>>(src, dst,
        W1_self, W1_neigh, W2_self, W2_neigh);

    int agg_grid  = (NN + 7) / 8;
    int gemm_grid = (NN + 127) / 128;

    // layer 1
    agg_kernel<<<agg_grid, 256>>>(in_feat, mean_p);
    gemm_mma_kernel<<<gemm_grid, 256, GSMEM>>>(in_feat, mean_p, whi_p, wlo_p, b1, h_p, 1);
    // layer 2
    agg_kernel<<<agg_grid, 256>>>(h_p, mean_p);
    gemm_mma_kernel<<<gemm_grid, 256, GSMEM>>>(h_p, mean_p, whi_p + 256 * DD, wlo_p + 256 * DD, b2, out, 0);
}

// round 10
// speedup vs baseline: 1.0897x; 1.0897x over previous
#include <cuda_runtime.h>
#include <cuda_bf16.h>
#include <cstdint>

#define NN 100000
#define EE 1600000
#define DD 128
#define NB 98            // ceil(NN/1024)

// ---------------- scratch (device globals: no allocation allowed) ----------------
__device__ int   g_counts[NN];
__device__ int   g_offsets[NN];
__device__ float g_deginv[NN];
__device__ int   g_bsums[128];
__device__ int   g_rank[EE];          // edge's rank within its dst bucket (from hist)
__device__ int   g_csr_src[EE];
__device__ float g_mean[(size_t)NN * DD];
__device__ float g_h[(size_t)NN * DD];
// preconverted weights hi/lo: [layer][256][128] (rows 0-127 = Wself, 128-255 = Wneigh)
__device__ __nv_bfloat16 g_whi[2 * 256 * DD];
__device__ __nv_bfloat16 g_wlo[2 * 256 * DD];

// ---------------- CSR build ----------------
// hist also records each edge's intra-bucket rank (the atomic's return value),
// so the scatter pass needs NO atomics.
__global__ void hist_kernel(const int* __restrict__ dst) {
    int i = blockIdx.x * blockDim.x + threadIdx.x;
    if (i < EE) g_rank[i] = atomicAdd(&g_counts[dst[i]], 1);
}

__global__ void scan_local_kernel() {
    __shared__ int wsums[32];
    int tid = threadIdx.x, lane = tid & 31, warp = tid >> 5;
    int i = blockIdx.x * 1024 + tid;
    int v = (i < NN) ? g_counts[i] : 0;
    int x = v;
    #pragma unroll
    for (int o = 1; o < 32; o <<= 1) {
        int t = __shfl_up_sync(0xffffffffu, x, o);
        if (lane >= o) x += t;
    }
    if (lane == 31) wsums[warp] = x;
    __syncthreads();
    if (warp == 0) {
        int w = wsums[lane];
        #pragma unroll
        for (int o = 1; o < 32; o <<= 1) {
            int t = __shfl_up_sync(0xffffffffu, w, o);
            if (lane >= o) w += t;
        }
        wsums[lane] = w;
    }
    __syncthreads();
    int incl = x + (warp ? wsums[warp - 1] : 0);
    if (i < NN) g_offsets[i] = incl - v;               // block-local exclusive
    if (tid == 1023) g_bsums[blockIdx.x] = incl;       // block total
}

// finalize with fused block-sums scan (each block redundantly scans the 98 sums)
__global__ void finalize_kernel() {
    __shared__ int pref[NB];
    int tid = threadIdx.x;
    if (tid < NB) pref[tid] = g_bsums[tid];
    __syncthreads();
    if (tid == 0) {
        int run = 0;
        #pragma unroll 7
        for (int j = 0; j < NB; ++j) { int t = pref[j]; pref[j] = run; run += t; }
    }
    __syncthreads();
    int i = blockIdx.x * blockDim.x + tid;
    if (i < NN) {
        int off = g_offsets[i] + pref[i >> 10];
        g_offsets[i] = off;
        int c = g_counts[i];
        g_deginv[i]  = 1.0f / (float)((c > 1) ? c : 1);
    }
}

// atomic-free scatter + fused weight hi/lo preconversion (extra 64 blocks)
#define SC_BLOCKS ((EE + 255) / 256)
__global__ void scatter_fused_kernel(const int* __restrict__ src, const int* __restrict__ dst,
                                     const float* __restrict__ W1s, const float* __restrict__ W1n,
                                     const float* __restrict__ W2s, const float* __restrict__ W2n) {
    if (blockIdx.x < SC_BLOCKS) {
        int i = blockIdx.x * 256 + threadIdx.x;
        if (i < EE) {
            int d = dst[i];
            int p = __ldg(&g_offsets[d]) + g_rank[i];
            g_csr_src[p] = src[i];
        }
    } else {
        int i = (blockIdx.x - SC_BLOCKS) * 256 + threadIdx.x;  // float4 index, 16384 total
        if (i >= 16384) return;
        int layer = i >> 13;
        int r256  = (i >> 5) & 255;
        int c4    = i & 31;
        const float* Wsrc = (layer == 0)
            ? ((r256 < 128) ? W1s + (size_t)r256 * DD : W1n + (size_t)(r256 - 128) * DD)
            : ((r256 < 128) ? W2s + (size_t)r256 * DD : W2n + (size_t)(r256 - 128) * DD);
        float4 v = *reinterpret_cast<const float4*>(Wsrc + c4 * 4);
        float hx = __bfloat162float(__float2bfloat16_rn(v.x));
        float hy = __bfloat162float(__float2bfloat16_rn(v.y));
        float hz = __bfloat162float(__float2bfloat16_rn(v.z));
        float hw = __bfloat162float(__float2bfloat16_rn(v.w));
        __nv_bfloat162 h0 = __floats2bfloat162_rn(v.x, v.y);
        __nv_bfloat162 h1 = __floats2bfloat162_rn(v.z, v.w);
        __nv_bfloat162 l0 = __floats2bfloat162_rn(v.x - hx, v.y - hy);
        __nv_bfloat162 l1 = __floats2bfloat162_rn(v.z - hz, v.w - hw);
        reinterpret_cast<uint2*>(g_whi)[i] = make_uint2(*(uint32_t*)&h0, *(uint32_t*)&h1);
        reinterpret_cast<uint2*>(g_wlo)[i] = make_uint2(*(uint32_t*)&l0, *(uint32_t*)&l1);
    }
}

// -------- mean aggregation: warp per node, edge-unroll x8 (FROZEN R5/R7 form) ----
__global__ void agg_kernel(const float* __restrict__ x, float* __restrict__ outmean) {
    int node = (blockIdx.x * blockDim.x + threadIdx.x) >> 5;
    int lane = threadIdx.x & 31;
    if (node >= NN) return;
    int s   = g_offsets[node];
    int cnt = g_counts[node];
    float a0 = 0.f, a1 = 0.f, a2 = 0.f, a3 = 0.f;
    int t = 0;
    for (; t + 8 <= cnt; t += 8) {
        int idx[8];
        #pragma unroll
        for (int u = 0; u < 8; ++u) idx[u] = __ldg(&g_csr_src[s + t + u]);
        float4 v[8];
        #pragma unroll
        for (int u = 0; u < 8; ++u)
            v[u] = __ldg(reinterpret_cast<const float4*>(x + (size_t)idx[u] * DD + lane * 4));
        #pragma unroll
        for (int u = 0; u < 8; ++u) {
            a0 += v[u].x; a1 += v[u].y; a2 += v[u].z; a3 += v[u].w;
        }
    }
    for (; t < cnt; ++t) {
        int i0 = __ldg(&g_csr_src[s + t]);
        float4 v = __ldg(reinterpret_cast<const float4*>(x + (size_t)i0 * DD + lane * 4));
        a0 += v.x; a1 += v.y; a2 += v.z; a3 += v.w;
    }
    float di = g_deginv[node];
    float4 o = make_float4(a0 * di, a1 * di, a2 * di, a3 * di);
    *reinterpret_cast<float4*>(outmean + (size_t)node * DD + lane * 4) = o;
}

// ====== tensor-core GEMM: double-buffered smem + register-prefetched A ======
__device__ __forceinline__ uint32_t smem_u32(const void* p) {
    uint32_t a;
    asm("{ .reg .u64 t; cvta.to.shared.u64 t, %1; cvt.u32.u64 %0, t; }" : "=r"(a) : "l"(p));
    return a;
}
__device__ __forceinline__ void ldsm_x4(uint32_t& r0, uint32_t& r1, uint32_t& r2, uint32_t& r3, uint32_t a) {
    asm volatile("ldmatrix.sync.aligned.m8n8.x4.shared.b16 {%0,%1,%2,%3}, [%4];"
                 : "=r"(r0), "=r"(r1), "=r"(r2), "=r"(r3) : "r"(a));
}
__device__ __forceinline__ void ldsm_x4_t(uint32_t& r0, uint32_t& r1, uint32_t& r2, uint32_t& r3, uint32_t a) {
    asm volatile("ldmatrix.sync.aligned.m8n8.x4.trans.shared.b16 {%0,%1,%2,%3}, [%4];"
                 : "=r"(r0), "=r"(r1), "=r"(r2), "=r"(r3) : "r"(a));
}
__device__ __forceinline__ void mma_bf16(float* c, uint32_t a0, uint32_t a1, uint32_t a2, uint32_t a3,
                                         uint32_t b0, uint32_t b1) {
    asm volatile("mma.sync.aligned.m16n8k16.row.col.f32.bf16.bf16.f32 "
                 "{%0,%1,%2,%3}, {%4,%5,%6,%7}, {%8,%9}, {%0,%1,%2,%3};"
                 : "+f"(c[0]), "+f"(c[1]), "+f"(c[2]), "+f"(c[3])
                 : "r"(a0), "r"(a1), "r"(a2), "r"(a3), "r"(b0), "r"(b1));
}
__device__ __forceinline__ uint32_t pack_bf2(float x, float y) {
    __nv_bfloat162 t = __floats2bfloat162_rn(x, y);
    return *reinterpret_cast<uint32_t*>(&t);
}

#define APAD 40
#define BPAD 136
// byte offsets within one buffer
#define OFF_AH 0
#define OFF_AL 10240
#define OFF_BH 20480
#define OFF_BL 29184
#define BUFSZ  37888
#define GSMEM  (2 * BUFSZ)

__global__ __launch_bounds__(256, 2) void gemm_mma_kernel(
    const float* __restrict__ A1, const float* __restrict__ A2,
    const __nv_bfloat16* __restrict__ Wh, const __nv_bfloat16* __restrict__ Wl,
    const float* __restrict__ bias, float* __restrict__ out, int relu)
{
    extern __shared__ char smem[];
    int tid = threadIdx.x, lane = tid & 31, wid = tid >> 5;
    int warp_m = wid & 3;
    int warp_n = wid >> 2;
    int m0 = blockIdx.x * 128;
    uint32_t sb = smem_u32(smem);

    float acc[2][8][4];
    #pragma unroll
    for (int i = 0; i < 2; ++i)
        #pragma unroll
        for (int j = 0; j < 8; ++j)
            #pragma unroll
            for (int q = 0; q < 4; ++q) acc[i][j][q] = 0.f;

    int a_lrow = lane & 15;
    int a_lcol = (lane >> 4) << 3;
    int b_lk   = lane & 15;
    int b_ln   = (lane >> 4) << 3;

    float4 av[4];
    // ---- prologue: load + store chunk 0 into buffer 0 ----
    #pragma unroll
    for (int i = 0; i < 4; ++i) {
        int f = tid + i * 256;
        int row = f >> 3, c4 = (f & 7) * 4;
        int gm = m0 + row;
        av[i] = (gm < NN) ? __ldg(reinterpret_cast<const float4*>(A1 + (size_t)gm * DD + c4))
                          : make_float4(0.f, 0.f, 0.f, 0.f);
    }
    {
        char* base = smem;   // buffer 0
        #pragma unroll
        for (int i = 0; i < 4; ++i) {
            int f = tid + i * 256;
            int row = f >> 3, c4 = (f & 7) * 4;
            float4 v = av[i];
            float hx = __bfloat162float(__float2bfloat16_rn(v.x));
            float hy = __bfloat162float(__float2bfloat16_rn(v.y));
            float hz = __bfloat162float(__float2bfloat16_rn(v.z));
            float hw = __bfloat162float(__float2bfloat16_rn(v.w));
            uint32_t off = (uint32_t)(row * APAD + c4) * 2;
            uint32_t* ph = reinterpret_cast<uint32_t*>(base + OFF_AH + off);
            ph[0] = pack_bf2(v.x, v.y); ph[1] = pack_bf2(v.z, v.w);
            uint32_t* pl = reinterpret_cast<uint32_t*>(base + OFF_AL + off);
            pl[0] = pack_bf2(v.x - hx, v.y - hy); pl[1] = pack_bf2(v.z - hz, v.w - hw);
        }
        #pragma unroll
        for (int i = 0; i < 4; ++i) {
            int u = tid + i * 256;
            int bufb = u >> 9, kr = (u >> 4) & 31, n8 = (u & 15) * 8;
            const __nv_bfloat16* s = bufb ? Wl : Wh;
            uint4 v = __ldg(reinterpret_cast<const uint4*>(s + (size_t)kr * DD + n8));
            *reinterpret_cast<uint4*>(base + (bufb ? OFF_BL : OFF_BH) + (uint32_t)(kr * BPAD + n8) * 2) = v;
        }
    }
    __syncthreads();

    for (int ch = 0; ch < 8; ++ch) {
        // ---- prefetch next chunk's A into registers (latency hides under MMA) ----
        float4 av2[4];
        if (ch < 7) {
            const float* Abase = (ch + 1 < 4) ? A1 : A2;
            int cb = ((ch + 1) & 3) * 32;
            #pragma unroll
            for (int i = 0; i < 4; ++i) {
                int f = tid + i * 256;
                int row = f >> 3, c4 = (f & 7) * 4;
                int gm = m0 + row;
                av2[i] = (gm < NN) ? __ldg(reinterpret_cast<const float4*>(Abase + (size_t)gm * DD + cb + c4))
                                   : make_float4(0.f, 0.f, 0.f, 0.f);
            }
        }

        // ---- compute from buffer ch&1 ----
        uint32_t bufbase = sb + (uint32_t)(ch & 1) * BUFSZ;
        uint32_t ah_b = bufbase + OFF_AH;
        uint32_t al_b = bufbase + OFF_AL;
        uint32_t bh_b = bufbase + OFF_BH;
        uint32_t bl_b = bufbase + OFF_BL;

        #pragma unroll
        for (int p = 0; p < 3; ++p) {
            uint32_t ab = (p == 1) ? al_b : ah_b;
            uint32_t bb = (p == 2) ? bl_b : bh_b;
            #pragma unroll
            for (int ks = 0; ks < 2; ++ks) {
                uint32_t a[2][4];
                #pragma unroll
                for (int mt = 0; mt < 2; ++mt) {
                    int row = warp_m * 32 + mt * 16 + a_lrow;
                    int col = ks * 16 + a_lcol;
                    ldsm_x4(a[mt][0], a[mt][1], a[mt][2], a[mt][3],
                            ab + (uint32_t)(row * APAD + col) * 2);
                }
                #pragma unroll
                for (int ng = 0; ng < 4; ++ng) {
                    int kk = ks * 16 + b_lk;
                    int nn = warp_n * 64 + ng * 16 + b_ln;
                    uint32_t b0, b1, b2, b3;
                    ldsm_x4_t(b0, b1, b2, b3, bb + (uint32_t)(kk * BPAD + nn) * 2);
                    #pragma unroll
                    for (int mt = 0; mt < 2; ++mt) {
                        mma_bf16(acc[mt][ng * 2 + 0], a[mt][0], a[mt][1], a[mt][2], a[mt][3], b0, b1);
                        mma_bf16(acc[mt][ng * 2 + 1], a[mt][0], a[mt][1], a[mt][2], a[mt][3], b2, b3);
                    }
                }
            }
        }

        // ---- convert + store next chunk into other buffer ----
        if (ch < 7) {
            char* base = smem + ((ch + 1) & 1) * BUFSZ;
            #pragma unroll
            for (int i = 0; i < 4; ++i) {
                int f = tid + i * 256;
                int row = f >> 3, c4 = (f & 7) * 4;
                float4 v = av2[i];
                float hx = __bfloat162float(__float2bfloat16_rn(v.x));
                float hy = __bfloat162float(__float2bfloat16_rn(v.y));
                float hz = __bfloat162float(__float2bfloat16_rn(v.z));
                float hw = __bfloat162float(__float2bfloat16_rn(v.w));
                uint32_t off = (uint32_t)(row * APAD + c4) * 2;
                uint32_t* ph = reinterpret_cast<uint32_t*>(base + OFF_AH + off);
                ph[0] = pack_bf2(v.x, v.y); ph[1] = pack_bf2(v.z, v.w);
                uint32_t* pl = reinterpret_cast<uint32_t*>(base + OFF_AL + off);
                pl[0] = pack_bf2(v.x - hx, v.y - hy); pl[1] = pack_bf2(v.z - hz, v.w - hw);
            }
            #pragma unroll
            for (int i = 0; i < 4; ++i) {
                int u = tid + i * 256;
                int bufb = u >> 9, kr = (u >> 4) & 31, n8 = (u & 15) * 8;
                const __nv_bfloat16* s = bufb ? Wl : Wh;
                uint4 v = __ldg(reinterpret_cast<const uint4*>(s + (size_t)((ch + 1) * 32 + kr) * DD + n8));
                *reinterpret_cast<uint4*>(base + (bufb ? OFF_BL : OFF_BH) + (uint32_t)(kr * BPAD + n8) * 2) = v;
            }
            __syncthreads();
        }
    }

    // --- epilogue ---
    int crow = lane >> 2;
    int ccol = (lane & 3) * 2;
    #pragma unroll
    for (int mt = 0; mt < 2; ++mt) {
        #pragma unroll
        for (int nt = 0; nt < 8; ++nt) {
            int col = warp_n * 64 + nt * 8 + ccol;
            float2 bb = __ldg(reinterpret_cast<const float2*>(bias + col));
            #pragma unroll
            for (int h = 0; h < 2; ++h) {
                int row = m0 + warp_m * 32 + mt * 16 + crow + h * 8;
                if (row >= NN) continue;
                float lo = acc[mt][nt][h * 2 + 0] + bb.x;
                float hi = acc[mt][nt][h * 2 + 1] + bb.y;
                if (relu) { lo = fmaxf(lo, 0.f); hi = fmaxf(hi, 0.f); }
                *reinterpret_cast<float2*>(out + (size_t)row * DD + col) = make_float2(lo, hi);
            }
        }
    }
}

// ---------------- launch ----------------
extern "C" void kernel_launch(void* const* d_in, const int* in_sizes, int n_in,
                              void* d_out, int out_size) {
    const float* in_feat  = (const float*)d_in[0];
    const float* W1_self  = (const float*)d_in[1];
    const float* W1_neigh = (const float*)d_in[2];
    const float* b1       = (const float*)d_in[3];
    const float* W2_self  = (const float*)d_in[4];
    const float* W2_neigh = (const float*)d_in[5];
    const float* b2       = (const float*)d_in[6];
    const int*   src      = (const int*)d_in[7];
    const int*   dst      = (const int*)d_in[8];
    float* out = (float*)d_out;

    int* counts_p;
    float *mean_p, *h_p;
    __nv_bfloat16 *whi_p, *wlo_p;
    cudaGetSymbolAddress((void**)&counts_p, g_counts);
    cudaGetSymbolAddress((void**)&mean_p, g_mean);
    cudaGetSymbolAddress((void**)&h_p, g_h);
    cudaGetSymbolAddress((void**)&whi_p, g_whi);
    cudaGetSymbolAddress((void**)&wlo_p, g_wlo);

    cudaFuncSetAttribute(gemm_mma_kernel, cudaFuncAttributeMaxDynamicSharedMemorySize, GSMEM);

    cudaMemsetAsync(counts_p, 0, NN * sizeof(int));

    hist_kernel<<<(EE + 255) / 256, 256>>>(dst);
    scan_local_kernel<<<NB, 1024>>>();
    finalize_kernel<<<(NN + 255) / 256, 256>>>();
    scatter_fused_kernel<<<SC_BLOCKS + 64, 256>>>(src, dst,
        W1_self, W1_neigh, W2_self, W2_neigh);

    int agg_grid  = (NN + 7) / 8;
    int gemm_grid = (NN + 127) / 128;

    // layer 1
    agg_kernel<<<agg_grid, 256>>>(in_feat, mean_p);
    gemm_mma_kernel<<<gemm_grid, 256, GSMEM>>>(in_feat, mean_p, whi_p, wlo_p, b1, h_p, 1);
    // layer 2
    agg_kernel<<<agg_grid, 256>>>(h_p, mean_p);
    gemm_mma_kernel<<<gemm_grid, 256, GSMEM>>>(h_p, mean_p, whi_p + 256 * DD, wlo_p + 256 * DD, b2, out, 0);
}

// round 12
// speedup vs baseline: 1.2783x; 1.1731x over previous
#include <cuda_runtime.h>
#include <cuda_bf16.h>
#include <cstdint>

#define NN 100000
#define EE 1600000
#define DD 128
#define NB 98            // ceil(NN/1024)

// ---------------- scratch (device globals: no allocation allowed) ----------------
__device__ int   g_counts[NN];
__device__ int   g_offsets[NN];
__device__ float g_deginv[NN];
__device__ int   g_bsums[128];
__device__ int   g_rank[EE];          // edge's rank within its dst bucket (from hist)
__device__ int   g_csr_src[EE];
__device__ float g_mean[(size_t)NN * DD];
__device__ float g_h[(size_t)NN * DD];
// pre-transposed tf32 weights: [layer][n=128][k=256] (k 0-127 = Wself, 128-255 = Wneigh)
__device__ float g_wt[2 * 128 * 256];

// ---------------- CSR build ----------------
// hist records each edge's intra-bucket rank so scatter needs NO atomics.
__global__ void hist_kernel(const int* __restrict__ dst) {
    int i = blockIdx.x * blockDim.x + threadIdx.x;
    if (i < EE) g_rank[i] = atomicAdd(&g_counts[dst[i]], 1);
}

__global__ void scan_local_kernel() {
    __shared__ int wsums[32];
    int tid = threadIdx.x, lane = tid & 31, warp = tid >> 5;
    int i = blockIdx.x * 1024 + tid;
    int v = (i < NN) ? g_counts[i] : 0;
    int x = v;
    #pragma unroll
    for (int o = 1; o < 32; o <<= 1) {
        int t = __shfl_up_sync(0xffffffffu, x, o);
        if (lane >= o) x += t;
    }
    if (lane == 31) wsums[warp] = x;
    __syncthreads();
    if (warp == 0) {
        int w = wsums[lane];
        #pragma unroll
        for (int o = 1; o < 32; o <<= 1) {
            int t = __shfl_up_sync(0xffffffffu, w, o);
            if (lane >= o) w += t;
        }
        wsums[lane] = w;
    }
    __syncthreads();
    int incl = x + (warp ? wsums[warp - 1] : 0);
    if (i < NN) g_offsets[i] = incl - v;               // block-local exclusive
    if (tid == 1023) g_bsums[blockIdx.x] = incl;       // block total
}

// finalize with fused block-sums scan
__global__ void finalize_kernel() {
    __shared__ int pref[NB];
    int tid = threadIdx.x;
    if (tid < NB) pref[tid] = g_bsums[tid];
    __syncthreads();
    if (tid == 0) {
        int run = 0;
        #pragma unroll 7
        for (int j = 0; j < NB; ++j) { int t = pref[j]; pref[j] = run; run += t; }
    }
    __syncthreads();
    int i = blockIdx.x * blockDim.x + tid;
    if (i < NN) {
        int off = g_offsets[i] + pref[i >> 10];
        g_offsets[i] = off;
        int c = g_counts[i];
        g_deginv[i]  = 1.0f / (float)((c > 1) ? c : 1);
    }
}

// atomic-free scatter + fused W transpose+tf32 conversion (extra 256 blocks)
#define SC_BLOCKS ((EE + 255) / 256)
__global__ void scatter_fused_kernel(const int* __restrict__ src, const int* __restrict__ dst,
                                     const float* __restrict__ W1s, const float* __restrict__ W1n,
                                     const float* __restrict__ W2s, const float* __restrict__ W2n) {
    if (blockIdx.x < SC_BLOCKS) {
        int i = blockIdx.x * 256 + threadIdx.x;
        if (i < EE) {
            int d = dst[i];
            int p = __ldg(&g_offsets[d]) + g_rank[i];
            g_csr_src[p] = src[i];
        }
    } else {
        // g_wt[layer][n][k] = cvt.rna.tf32( W[layer][self/neigh][k][n] ), 65536 elems
        int i = (blockIdx.x - SC_BLOCKS) * 256 + threadIdx.x;
        if (i >= 65536) return;
        int layer = i >> 15;
        int n = (i >> 8) & 127;
        int k = i & 255;
        const float* Wsrc = (layer == 0)
            ? ((k < 128) ? W1s + (size_t)k * DD : W1n + (size_t)(k - 128) * DD)
            : ((k < 128) ? W2s + (size_t)k * DD : W2n + (size_t)(k - 128) * DD);
        float v = __ldg(&Wsrc[n]);
        uint32_t t;
        asm("cvt.rna.tf32.f32 %0, %1;" : "=r"(t) : "f"(v));
        reinterpret_cast<uint32_t*>(g_wt)[i] = t;
    }
}

// -------- mean aggregation: warp per node, edge-unroll x8 (FROZEN R5/R7 form) ----
__global__ void agg_kernel(const float* __restrict__ x, float* __restrict__ outmean) {
    int node = (blockIdx.x * blockDim.x + threadIdx.x) >> 5;
    int lane = threadIdx.x & 31;
    if (node >= NN) return;
    int s   = g_offsets[node];
    int cnt = g_counts[node];
    float a0 = 0.f, a1 = 0.f, a2 = 0.f, a3 = 0.f;
    int t = 0;
    for (; t + 8 <= cnt; t += 8) {
        int idx[8];
        #pragma unroll
        for (int u = 0; u < 8; ++u) idx[u] = __ldg(&g_csr_src[s + t + u]);
        float4 v[8];
        #pragma unroll
        for (int u = 0; u < 8; ++u)
            v[u] = __ldg(reinterpret_cast<const float4*>(x + (size_t)idx[u] * DD + lane * 4));
        #pragma unroll
        for (int u = 0; u < 8; ++u) {
            a0 += v[u].x; a1 += v[u].y; a2 += v[u].z; a3 += v[u].w;
        }
    }
    for (; t < cnt; ++t) {
        int i0 = __ldg(&g_csr_src[s + t]);
        float4 v = __ldg(reinterpret_cast<const float4*>(x + (size_t)i0 * DD + lane * 4));
        a0 += v.x; a1 += v.y; a2 += v.z; a3 += v.w;
    }
    float di = g_deginv[node];
    float4 o = make_float4(a0 * di, a1 * di, a2 * di, a3 * di);
    *reinterpret_cast<float4*>(outmean + (size_t)node * DD + lane * 4) = o;
}

// ====== TF32 tensor-core GEMM: single product, double-buffered + prefetch ======
__device__ __forceinline__ uint32_t smem_u32(const void* p) {
    uint32_t a;
    asm("{ .reg .u64 t; cvta.to.shared.u64 t, %1; cvt.u32.u64 %0, t; }" : "=r"(a) : "l"(p));
    return a;
}
__device__ __forceinline__ void ldsm_x4(uint32_t& r0, uint32_t& r1, uint32_t& r2, uint32_t& r3, uint32_t a) {
    asm volatile("ldmatrix.sync.aligned.m8n8.x4.shared.b16 {%0,%1,%2,%3}, [%4];"
                 : "=r"(r0), "=r"(r1), "=r"(r2), "=r"(r3) : "r"(a));
}
__device__ __forceinline__ void mma_tf32(float* c, uint32_t a0, uint32_t a1, uint32_t a2, uint32_t a3,
                                         uint32_t b0, uint32_t b1) {
    asm volatile("mma.sync.aligned.m16n8k8.row.col.f32.tf32.tf32.f32 "
                 "{%0,%1,%2,%3}, {%4,%5,%6,%7}, {%8,%9}, {%0,%1,%2,%3};"
                 : "+f"(c[0]), "+f"(c[1]), "+f"(c[2]), "+f"(c[3])
                 : "r"(a0), "r"(a1), "r"(a2), "r"(a3), "r"(b0), "r"(b1));
}
__device__ __forceinline__ uint32_t cvt_tf32(float v) {
    uint32_t t;
    asm("cvt.rna.tf32.f32 %0, %1;" : "=r"(t) : "f"(v));
    return t;
}

// rows padded to 144 bytes (32 tf32 = 128B data + 16B pad): 16B-aligned, bank-rotating
#define RSTRIDE 144
#define OFF_A 0
#define OFF_B 18432          // 128 * 144
#define BUFSZ 36864
#define GSMEM (2 * BUFSZ)

__global__ __launch_bounds__(256, 2) void gemm_mma_kernel(
    const float* __restrict__ A1, const float* __restrict__ A2,
    const float* __restrict__ Wt,    // [128 n][256 k] tf32 bits
    const float* __restrict__ bias, float* __restrict__ out, int relu)
{
    extern __shared__ char smem[];
    int tid = threadIdx.x, lane = tid & 31, wid = tid >> 5;
    int warp_m = wid & 3;            // rows warp_m*32
    int warp_n = wid >> 2;           // cols warp_n*64
    int m0 = blockIdx.x * 128;
    uint32_t sb = smem_u32(smem);

    float acc[2][8][4];
    #pragma unroll
    for (int i = 0; i < 2; ++i)
        #pragma unroll
        for (int j = 0; j < 8; ++j)
            #pragma unroll
            for (int q = 0; q < 4; ++q) acc[i][j][q] = 0.f;

    int lrow   = lane & 15;          // ldmatrix row within 16
    int lkoff  = (lane >> 4) * 16;   // byte offset: 0 or 16 (4 tf32)

    float4 av[4];
    // ---- prologue: load + convert + store chunk 0 into buffer 0 ----
    #pragma unroll
    for (int i = 0; i < 4; ++i) {
        int f = tid + i * 256;
        int row = f >> 3, c4 = (f & 7) * 4;
        int gm = m0 + row;
        av[i] = (gm < NN) ? __ldg(reinterpret_cast<const float4*>(A1 + (size_t)gm * DD + c4))
                          : make_float4(0.f, 0.f, 0.f, 0.f);
    }
    {
        char* base = smem;
        #pragma unroll
        for (int i = 0; i < 4; ++i) {
            int f = tid + i * 256;
            int row = f >> 3, c4 = (f & 7) * 4;
            uint4 t = make_uint4(cvt_tf32(av[i].x), cvt_tf32(av[i].y),
                                 cvt_tf32(av[i].z), cvt_tf32(av[i].w));
            *reinterpret_cast<uint4*>(base + OFF_A + row * RSTRIDE + c4 * 4) = t;
        }
        #pragma unroll
        for (int i = 0; i < 4; ++i) {
            int u = tid + i * 256;
            int n = u >> 3, kc = (u & 7) * 4;
            uint4 v = __ldg(reinterpret_cast<const uint4*>(Wt + (size_t)n * 256 + kc));
            *reinterpret_cast<uint4*>(base + OFF_B + n * RSTRIDE + kc * 4) = v;
        }
    }
    __syncthreads();

    for (int ch = 0; ch < 8; ++ch) {
        // ---- prefetch next chunk's A into registers ----
        float4 av2[4];
        if (ch < 7) {
            const float* Abase = (ch + 1 < 4) ? A1 : A2;
            int cb = ((ch + 1) & 3) * 32;
            #pragma unroll
            for (int i = 0; i < 4; ++i) {
                int f = tid + i * 256;
                int row = f >> 3, c4 = (f & 7) * 4;
                int gm = m0 + row;
                av2[i] = (gm < NN) ? __ldg(reinterpret_cast<const float4*>(Abase + (size_t)gm * DD + cb + c4))
                                   : make_float4(0.f, 0.f, 0.f, 0.f);
            }
        }

        // ---- compute from buffer ch&1 ----
        uint32_t bufbase = sb + (uint32_t)(ch & 1) * BUFSZ;
        uint32_t a_b = bufbase + OFF_A;
        uint32_t b_b = bufbase + OFF_B;

        #pragma unroll
        for (int ks = 0; ks < 4; ++ks) {                 // 4 k-steps of 8 tf32
            uint32_t a[2][4];
            #pragma unroll
            for (int mt = 0; mt < 2; ++mt) {
                int row = warp_m * 32 + mt * 16 + lrow;
                ldsm_x4(a[mt][0], a[mt][1], a[mt][2], a[mt][3],
                        a_b + (uint32_t)(row * RSTRIDE) + ks * 32 + lkoff);
            }
            #pragma unroll
            for (int np = 0; np < 4; ++np) {             // 4 n-pairs of 16
                int n = warp_n * 64 + np * 16 + lrow;
                uint32_t b0, b1, b2, b3;                 // b0/b2 -> nt even, b1/b3 -> nt odd
                ldsm_x4(b0, b1, b2, b3,
                        b_b + (uint32_t)(n * RSTRIDE) + ks * 32 + lkoff);
                #pragma unroll
                for (int mt = 0; mt < 2; ++mt) {
                    mma_tf32(acc[mt][np * 2 + 0], a[mt][0], a[mt][1], a[mt][2], a[mt][3], b0, b2);
                    mma_tf32(acc[mt][np * 2 + 1], a[mt][0], a[mt][1], a[mt][2], a[mt][3], b1, b3);
                }
            }
        }

        // ---- convert + store next chunk into other buffer ----
        if (ch < 7) {
            char* base = smem + ((ch + 1) & 1) * BUFSZ;
            #pragma unroll
            for (int i = 0; i < 4; ++i) {
                int f = tid + i * 256;
                int row = f >> 3, c4 = (f & 7) * 4;
                uint4 t = make_uint4(cvt_tf32(av2[i].x), cvt_tf32(av2[i].y),
                                     cvt_tf32(av2[i].z), cvt_tf32(av2[i].w));
                *reinterpret_cast<uint4*>(base + OFF_A + row * RSTRIDE + c4 * 4) = t;
            }
            #pragma unroll
            for (int i = 0; i < 4; ++i) {
                int u = tid + i * 256;
                int n = u >> 3, kc = (u & 7) * 4;
                uint4 v = __ldg(reinterpret_cast<const uint4*>(Wt + (size_t)n * 256 + (ch + 1) * 32 + kc));
                *reinterpret_cast<uint4*>(base + OFF_B + n * RSTRIDE + kc * 4) = v;
            }
            __syncthreads();
        }
    }

    // --- epilogue (same C-fragment layout as before) ---
    int crow = lane >> 2;
    int ccol = (lane & 3) * 2;
    #pragma unroll
    for (int mt = 0; mt < 2; ++mt) {
        #pragma unroll
        for (int nt = 0; nt < 8; ++nt) {
            int col = warp_n * 64 + nt * 8 + ccol;
            float2 bb = __ldg(reinterpret_cast<const float2*>(bias + col));
            #pragma unroll
            for (int h = 0; h < 2; ++h) {
                int row = m0 + warp_m * 32 + mt * 16 + crow + h * 8;
                if (row >= NN) continue;
                float lo = acc[mt][nt][h * 2 + 0] + bb.x;
                float hi = acc[mt][nt][h * 2 + 1] + bb.y;
                if (relu) { lo = fmaxf(lo, 0.f); hi = fmaxf(hi, 0.f); }
                *reinterpret_cast<float2*>(out + (size_t)row * DD + col) = make_float2(lo, hi);
            }
        }
    }
}

// ---------------- launch ----------------
extern "C" void kernel_launch(void* const* d_in, const int* in_sizes, int n_in,
                              void* d_out, int out_size) {
    const float* in_feat  = (const float*)d_in[0];
    const float* W1_self  = (const float*)d_in[1];
    const float* W1_neigh = (const float*)d_in[2];
    const float* b1       = (const float*)d_in[3];
    const float* W2_self  = (const float*)d_in[4];
    const float* W2_neigh = (const float*)d_in[5];
    const float* b2       = (const float*)d_in[6];
    const int*   src      = (const int*)d_in[7];
    const int*   dst      = (const int*)d_in[8];
    float* out = (float*)d_out;

    int* counts_p;
    float *mean_p, *h_p, *wt_p;
    cudaGetSymbolAddress((void**)&counts_p, g_counts);
    cudaGetSymbolAddress((void**)&mean_p, g_mean);
    cudaGetSymbolAddress((void**)&h_p, g_h);
    cudaGetSymbolAddress((void**)&wt_p, g_wt);

    cudaFuncSetAttribute(gemm_mma_kernel, cudaFuncAttributeMaxDynamicSharedMemorySize, GSMEM);

    cudaMemsetAsync(counts_p, 0, NN * sizeof(int));

    hist_kernel<<<(EE + 255) / 256, 256>>>(dst);
    scan_local_kernel<<<NB, 1024>>>();
    finalize_kernel<<<(NN + 255) / 256, 256>>>();
    scatter_fused_kernel<<<SC_BLOCKS + 256, 256>>>(src, dst,
        W1_self, W1_neigh, W2_self, W2_neigh);

    int agg_grid  = (NN + 7) / 8;
    int gemm_grid = (NN + 127) / 128;

    // layer 1
    agg_kernel<<<agg_grid, 256>>>(in_feat, mean_p);
    gemm_mma_kernel<<<gemm_grid, 256, GSMEM>>>(in_feat, mean_p, wt_p, b1, h_p, 1);
    // layer 2
    agg_kernel<<<agg_grid, 256>>>(h_p, mean_p);
    gemm_mma_kernel<<<gemm_grid, 256, GSMEM>>>(h_p, mean_p, wt_p + 128 * 256, b2, out, 0);
}

// round 13
// speedup vs baseline: 1.4898x; 1.1655x over previous
#include <cuda_runtime.h>
#include <cuda_fp16.h>
#include <cstdint>

#define NN 100000
#define EE 1600000
#define DD 128
#define NB 98            // ceil(NN/1024)

// ---------------- scratch (device globals: no allocation allowed) ----------------
__device__ int   g_counts[NN];
__device__ int   g_offsets[NN];
__device__ float g_deginv[NN];
__device__ int   g_bsums[128];
__device__ int   g_rank[EE];          // edge's rank within its dst bucket (from hist)
__device__ int   g_csr_src[EE];
__device__ float g_mean[(size_t)NN * DD];
__device__ float g_h[(size_t)NN * DD];
// preconverted fp16 weights: [layer][256 k][128 n] (k 0-127 = Wself, 128-255 = Wneigh)
__device__ __half g_wh[2 * 256 * DD];

// ---------------- CSR build ----------------
// hist records each edge's intra-bucket rank so scatter needs NO atomics.
__global__ void hist_kernel(const int* __restrict__ dst) {
    int i = blockIdx.x * blockDim.x + threadIdx.x;
    if (i < EE) g_rank[i] = atomicAdd(&g_counts[dst[i]], 1);
}

__global__ void scan_local_kernel() {
    __shared__ int wsums[32];
    int tid = threadIdx.x, lane = tid & 31, warp = tid >> 5;
    int i = blockIdx.x * 1024 + tid;
    int v = (i < NN) ? g_counts[i] : 0;
    int x = v;
    #pragma unroll
    for (int o = 1; o < 32; o <<= 1) {
        int t = __shfl_up_sync(0xffffffffu, x, o);
        if (lane >= o) x += t;
    }
    if (lane == 31) wsums[warp] = x;
    __syncthreads();
    if (warp == 0) {
        int w = wsums[lane];
        #pragma unroll
        for (int o = 1; o < 32; o <<= 1) {
            int t = __shfl_up_sync(0xffffffffu, w, o);
            if (lane >= o) w += t;
        }
        wsums[lane] = w;
    }
    __syncthreads();
    int incl = x + (warp ? wsums[warp - 1] : 0);
    if (i < NN) g_offsets[i] = incl - v;               // block-local exclusive
    if (tid == 1023) g_bsums[blockIdx.x] = incl;       // block total
}

// finalize with fused block-sums scan
__global__ void finalize_kernel() {
    __shared__ int pref[NB];
    int tid = threadIdx.x;
    if (tid < NB) pref[tid] = g_bsums[tid];
    __syncthreads();
    if (tid == 0) {
        int run = 0;
        #pragma unroll 7
        for (int j = 0; j < NB; ++j) { int t = pref[j]; pref[j] = run; run += t; }
    }
    __syncthreads();
    int i = blockIdx.x * blockDim.x + tid;
    if (i < NN) {
        int off = g_offsets[i] + pref[i >> 10];
        g_offsets[i] = off;
        int c = g_counts[i];
        g_deginv[i]  = 1.0f / (float)((c > 1) ? c : 1);
    }
}

// atomic-free scatter + fused W fp16 preconversion (extra 32 blocks)
#define SC_BLOCKS ((EE + 255) / 256)
__global__ void scatter_fused_kernel(const int* __restrict__ src, const int* __restrict__ dst,
                                     const float* __restrict__ W1s, const float* __restrict__ W1n,
                                     const float* __restrict__ W2s, const float* __restrict__ W2n) {
    if (blockIdx.x < SC_BLOCKS) {
        int i = blockIdx.x * 256 + threadIdx.x;
        if (i < EE) {
            int d = dst[i];
            int p = __ldg(&g_offsets[d]) + g_rank[i];
            g_csr_src[p] = src[i];
        }
    } else {
        // g_wh[layer][k][n] = fp16(W), 8192 float4 groups
        int i = (blockIdx.x - SC_BLOCKS) * 256 + threadIdx.x;
        if (i >= 16384) return;
        int layer = i >> 13;
        int r256  = (i >> 5) & 255;
        int c4    = i & 31;
        const float* Wsrc = (layer == 0)
            ? ((r256 < 128) ? W1s + (size_t)r256 * DD : W1n + (size_t)(r256 - 128) * DD)
            : ((r256 < 128) ? W2s + (size_t)r256 * DD : W2n + (size_t)(r256 - 128) * DD);
        float4 v = *reinterpret_cast<const float4*>(Wsrc + c4 * 4);
        __half2 h0 = __floats2half2_rn(v.x, v.y);
        __half2 h1 = __floats2half2_rn(v.z, v.w);
        reinterpret_cast<uint2*>(g_wh)[i] = make_uint2(*(uint32_t*)&h0, *(uint32_t*)&h1);
    }
}

// -------- mean aggregation: warp per node, edge-unroll x8 (FROZEN R5/R7 form) ----
__global__ void agg_kernel(const float* __restrict__ x, float* __restrict__ outmean) {
    int node = (blockIdx.x * blockDim.x + threadIdx.x) >> 5;
    int lane = threadIdx.x & 31;
    if (node >= NN) return;
    int s   = g_offsets[node];
    int cnt = g_counts[node];
    float a0 = 0.f, a1 = 0.f, a2 = 0.f, a3 = 0.f;
    int t = 0;
    for (; t + 8 <= cnt; t += 8) {
        int idx[8];
        #pragma unroll
        for (int u = 0; u < 8; ++u) idx[u] = __ldg(&g_csr_src[s + t + u]);
        float4 v[8];
        #pragma unroll
        for (int u = 0; u < 8; ++u)
            v[u] = __ldg(reinterpret_cast<const float4*>(x + (size_t)idx[u] * DD + lane * 4));
        #pragma unroll
        for (int u = 0; u < 8; ++u) {
            a0 += v[u].x; a1 += v[u].y; a2 += v[u].z; a3 += v[u].w;
        }
    }
    for (; t < cnt; ++t) {
        int i0 = __ldg(&g_csr_src[s + t]);
        float4 v = __ldg(reinterpret_cast<const float4*>(x + (size_t)i0 * DD + lane * 4));
        a0 += v.x; a1 += v.y; a2 += v.z; a3 += v.w;
    }
    float di = g_deginv[node];
    float4 o = make_float4(a0 * di, a1 * di, a2 * di, a3 * di);
    *reinterpret_cast<float4*>(outmean + (size_t)node * DD + lane * 4) = o;
}

// ====== fp16 single-product tensor-core GEMM: double-buffered + prefetch ======
__device__ __forceinline__ uint32_t smem_u32(const void* p) {
    uint32_t a;
    asm("{ .reg .u64 t; cvta.to.shared.u64 t, %1; cvt.u32.u64 %0, t; }" : "=r"(a) : "l"(p));
    return a;
}
__device__ __forceinline__ void ldsm_x4(uint32_t& r0, uint32_t& r1, uint32_t& r2, uint32_t& r3, uint32_t a) {
    asm volatile("ldmatrix.sync.aligned.m8n8.x4.shared.b16 {%0,%1,%2,%3}, [%4];"
                 : "=r"(r0), "=r"(r1), "=r"(r2), "=r"(r3) : "r"(a));
}
__device__ __forceinline__ void ldsm_x4_t(uint32_t& r0, uint32_t& r1, uint32_t& r2, uint32_t& r3, uint32_t a) {
    asm volatile("ldmatrix.sync.aligned.m8n8.x4.trans.shared.b16 {%0,%1,%2,%3}, [%4];"
                 : "=r"(r0), "=r"(r1), "=r"(r2), "=r"(r3) : "r"(a));
}
__device__ __forceinline__ void mma_fp16(float* c, uint32_t a0, uint32_t a1, uint32_t a2, uint32_t a3,
                                         uint32_t b0, uint32_t b1) {
    asm volatile("mma.sync.aligned.m16n8k16.row.col.f32.f16.f16.f32 "
                 "{%0,%1,%2,%3}, {%4,%5,%6,%7}, {%8,%9}, {%0,%1,%2,%3};"
                 : "+f"(c[0]), "+f"(c[1]), "+f"(c[2]), "+f"(c[3])
                 : "r"(a0), "r"(a1), "r"(a2), "r"(a3), "r"(b0), "r"(b1));
}
__device__ __forceinline__ uint32_t pack_h2(float x, float y) {
    __half2 t = __floats2half2_rn(x, y);
    return *reinterpret_cast<uint32_t*>(&t);
}

#define APAD 40
#define BPAD 136
// byte offsets within one buffer
#define OFF_A 0
#define OFF_B 10240          // 128*APAD*2
#define BUFSZ 18944          // OFF_B + 32*BPAD*2
#define GSMEM (2 * BUFSZ)

__global__ __launch_bounds__(256, 2) void gemm_mma_kernel(
    const float* __restrict__ A1, const float* __restrict__ A2,
    const __half* __restrict__ Wh,   // [256 k][128 n] fp16
    const float* __restrict__ bias, float* __restrict__ out, int relu)
{
    extern __shared__ char smem[];
    int tid = threadIdx.x, lane = tid & 31, wid = tid >> 5;
    int warp_m = wid & 3;
    int warp_n = wid >> 2;
    int m0 = blockIdx.x * 128;
    uint32_t sb = smem_u32(smem);

    float acc[2][8][4];
    #pragma unroll
    for (int i = 0; i < 2; ++i)
        #pragma unroll
        for (int j = 0; j < 8; ++j)
            #pragma unroll
            for (int q = 0; q < 4; ++q) acc[i][j][q] = 0.f;

    int a_lrow = lane & 15;
    int a_lcol = (lane >> 4) << 3;
    int b_lk   = lane & 15;
    int b_ln   = (lane >> 4) << 3;

    float4 av[4];
    // ---- prologue: load + convert + store chunk 0 into buffer 0 ----
    #pragma unroll
    for (int i = 0; i < 4; ++i) {
        int f = tid + i * 256;
        int row = f >> 3, c4 = (f & 7) * 4;
        int gm = m0 + row;
        av[i] = (gm < NN) ? __ldg(reinterpret_cast<const float4*>(A1 + (size_t)gm * DD + c4))
                          : make_float4(0.f, 0.f, 0.f, 0.f);
    }
    {
        char* base = smem;
        #pragma unroll
        for (int i = 0; i < 4; ++i) {
            int f = tid + i * 256;
            int row = f >> 3, c4 = (f & 7) * 4;
            uint32_t* p = reinterpret_cast<uint32_t*>(base + OFF_A + (uint32_t)(row * APAD + c4) * 2);
            p[0] = pack_h2(av[i].x, av[i].y);
            p[1] = pack_h2(av[i].z, av[i].w);
        }
        #pragma unroll
        for (int i = 0; i < 2; ++i) {
            int u = tid + i * 256;             // 0..511: 32 k-rows x 16 uint4-groups
            int kr = u >> 4, n8 = (u & 15) * 8;
            uint4 v = __ldg(reinterpret_cast<const uint4*>(Wh + (size_t)kr * DD + n8));
            *reinterpret_cast<uint4*>(base + OFF_B + (uint32_t)(kr * BPAD + n8) * 2) = v;
        }
    }
    __syncthreads();

    for (int ch = 0; ch < 8; ++ch) {
        // ---- prefetch next chunk's A into registers ----
        float4 av2[4];
        if (ch < 7) {
            const float* Abase = (ch + 1 < 4) ? A1 : A2;
            int cb = ((ch + 1) & 3) * 32;
            #pragma unroll
            for (int i = 0; i < 4; ++i) {
                int f = tid + i * 256;
                int row = f >> 3, c4 = (f & 7) * 4;
                int gm = m0 + row;
                av2[i] = (gm < NN) ? __ldg(reinterpret_cast<const float4*>(Abase + (size_t)gm * DD + cb + c4))
                                   : make_float4(0.f, 0.f, 0.f, 0.f);
            }
        }

        // ---- compute from buffer ch&1 ----
        uint32_t bufbase = sb + (uint32_t)(ch & 1) * BUFSZ;
        uint32_t a_b = bufbase + OFF_A;
        uint32_t b_b = bufbase + OFF_B;

        #pragma unroll
        for (int ks = 0; ks < 2; ++ks) {
            uint32_t a[2][4];
            #pragma unroll
            for (int mt = 0; mt < 2; ++mt) {
                int row = warp_m * 32 + mt * 16 + a_lrow;
                int col = ks * 16 + a_lcol;
                ldsm_x4(a[mt][0], a[mt][1], a[mt][2], a[mt][3],
                        a_b + (uint32_t)(row * APAD + col) * 2);
            }
            #pragma unroll
            for (int ng = 0; ng < 4; ++ng) {
                int kk = ks * 16 + b_lk;
                int nn = warp_n * 64 + ng * 16 + b_ln;
                uint32_t b0, b1, b2, b3;
                ldsm_x4_t(b0, b1, b2, b3, b_b + (uint32_t)(kk * BPAD + nn) * 2);
                #pragma unroll
                for (int mt = 0; mt < 2; ++mt) {
                    mma_fp16(acc[mt][ng * 2 + 0], a[mt][0], a[mt][1], a[mt][2], a[mt][3], b0, b1);
                    mma_fp16(acc[mt][ng * 2 + 1], a[mt][0], a[mt][1], a[mt][2], a[mt][3], b2, b3);
                }
            }
        }

        // ---- convert + store next chunk into other buffer ----
        if (ch < 7) {
            char* base = smem + ((ch + 1) & 1) * BUFSZ;
            #pragma unroll
            for (int i = 0; i < 4; ++i) {
                int f = tid + i * 256;
                int row = f >> 3, c4 = (f & 7) * 4;
                uint32_t* p = reinterpret_cast<uint32_t*>(base + OFF_A + (uint32_t)(row * APAD + c4) * 2);
                p[0] = pack_h2(av2[i].x, av2[i].y);
                p[1] = pack_h2(av2[i].z, av2[i].w);
            }
            #pragma unroll
            for (int i = 0; i < 2; ++i) {
                int u = tid + i * 256;
                int kr = u >> 4, n8 = (u & 15) * 8;
                uint4 v = __ldg(reinterpret_cast<const uint4*>(Wh + (size_t)((ch + 1) * 32 + kr) * DD + n8));
                *reinterpret_cast<uint4*>(base + OFF_B + (uint32_t)(kr * BPAD + n8) * 2) = v;
            }
            __syncthreads();
        }
    }

    // --- epilogue ---
    int crow = lane >> 2;
    int ccol = (lane & 3) * 2;
    #pragma unroll
    for (int mt = 0; mt < 2; ++mt) {
        #pragma unroll
        for (int nt = 0; nt < 8; ++nt) {
            int col = warp_n * 64 + nt * 8 + ccol;
            float2 bb = __ldg(reinterpret_cast<const float2*>(bias + col));
            #pragma unroll
            for (int h = 0; h < 2; ++h) {
                int row = m0 + warp_m * 32 + mt * 16 + crow + h * 8;
                if (row >= NN) continue;
                float lo = acc[mt][nt][h * 2 + 0] + bb.x;
                float hi = acc[mt][nt][h * 2 + 1] + bb.y;
                if (relu) { lo = fmaxf(lo, 0.f); hi = fmaxf(hi, 0.f); }
                *reinterpret_cast<float2*>(out + (size_t)row * DD + col) = make_float2(lo, hi);
            }
        }
    }
}

// ---------------- launch ----------------
extern "C" void kernel_launch(void* const* d_in, const int* in_sizes, int n_in,
                              void* d_out, int out_size) {
    const float* in_feat  = (const float*)d_in[0];
    const float* W1_self  = (const float*)d_in[1];
    const float* W1_neigh = (const float*)d_in[2];
    const float* b1       = (const float*)d_in[3];
    const float* W2_self  = (const float*)d_in[4];
    const float* W2_neigh = (const float*)d_in[5];
    const float* b2       = (const float*)d_in[6];
    const int*   src      = (const int*)d_in[7];
    const int*   dst      = (const int*)d_in[8];
    float* out = (float*)d_out;

    int* counts_p;
    float *mean_p, *h_p;
    __half* wh_p;
    cudaGetSymbolAddress((void**)&counts_p, g_counts);
    cudaGetSymbolAddress((void**)&mean_p, g_mean);
    cudaGetSymbolAddress((void**)&h_p, g_h);
    cudaGetSymbolAddress((void**)&wh_p, g_wh);

    cudaFuncSetAttribute(gemm_mma_kernel, cudaFuncAttributeMaxDynamicSharedMemorySize, GSMEM);

    cudaMemsetAsync(counts_p, 0, NN * sizeof(int));

    hist_kernel<<<(EE + 255) / 256, 256>>>(dst);
    scan_local_kernel<<<NB, 1024>>>();
    finalize_kernel<<<(NN + 255) / 256, 256>>>();
    scatter_fused_kernel<<<SC_BLOCKS + 64, 256>>>(src, dst,
        W1_self, W1_neigh, W2_self, W2_neigh);

    int agg_grid  = (NN + 7) / 8;
    int gemm_grid = (NN + 127) / 128;

    // layer 1
    agg_kernel<<<agg_grid, 256>>>(in_feat, mean_p);
    gemm_mma_kernel<<<gemm_grid, 256, GSMEM>>>(in_feat, mean_p, wh_p, b1, h_p, 1);
    // layer 2
    agg_kernel<<<agg_grid, 256>>>(h_p, mean_p);
    gemm_mma_kernel<<<gemm_grid, 256, GSMEM>>>(h_p, mean_p, wh_p + 256 * DD, b2, out, 0);
}

// round 14
// speedup vs baseline: 1.6624x; 1.1159x over previous
#include <cuda_runtime.h>
#include <cuda_fp16.h>
#include <cstdint>

#define NN 100000
#define EE 1600000
#define DD 128
#define NB 98            // ceil(NN/1024)

// ---------------- scratch (device globals: no allocation allowed) ----------------
__device__ int    g_counts[NN];
__device__ int    g_offsets[NN];
__device__ float  g_deginv[NN];
__device__ int    g_bsums[128];
__device__ int    g_rank[EE];         // edge's rank within its dst bucket (from hist)
__device__ int    g_csr_src[EE];
__device__ __half g_xh[(size_t)NN * DD];    // fp16 input features
__device__ __half g_mh[(size_t)NN * DD];    // fp16 neighbor means
__device__ __half g_hh[(size_t)NN * DD];    // fp16 layer-1 activations
// preconverted fp16 weights: [layer][256 k][128 n] (k 0-127 = Wself, 128-255 = Wneigh)
__device__ __half g_wh[2 * 256 * DD];

// ---------------- CSR build ----------------
// hist (records intra-bucket rank -> atomic-free scatter) + fused x->fp16 convert
#define HB ((EE + 255) / 256)
__global__ void hist_fused_kernel(const int* __restrict__ dst, const float* __restrict__ x) {
    if (blockIdx.x < HB) {
        int i = blockIdx.x * 256 + threadIdx.x;
        if (i < EE) g_rank[i] = atomicAdd(&g_counts[dst[i]], 1);
    } else {
        int i = (blockIdx.x - HB) * 256 + threadIdx.x;   // float4 index
        if (i < NN * DD / 4) {
            float4 v = __ldg(reinterpret_cast<const float4*>(x) + i);
            __half2 h0 = __floats2half2_rn(v.x, v.y);
            __half2 h1 = __floats2half2_rn(v.z, v.w);
            reinterpret_cast<uint2*>(g_xh)[i] = make_uint2(*(uint32_t*)&h0, *(uint32_t*)&h1);
        }
    }
}

__global__ void scan_local_kernel() {
    __shared__ int wsums[32];
    int tid = threadIdx.x, lane = tid & 31, warp = tid >> 5;
    int i = blockIdx.x * 1024 + tid;
    int v = (i < NN) ? g_counts[i] : 0;
    int x = v;
    #pragma unroll
    for (int o = 1; o < 32; o <<= 1) {
        int t = __shfl_up_sync(0xffffffffu, x, o);
        if (lane >= o) x += t;
    }
    if (lane == 31) wsums[warp] = x;
    __syncthreads();
    if (warp == 0) {
        int w = wsums[lane];
        #pragma unroll
        for (int o = 1; o < 32; o <<= 1) {
            int t = __shfl_up_sync(0xffffffffu, w, o);
            if (lane >= o) w += t;
        }
        wsums[lane] = w;
    }
    __syncthreads();
    int incl = x + (warp ? wsums[warp - 1] : 0);
    if (i < NN) g_offsets[i] = incl - v;               // block-local exclusive
    if (tid == 1023) g_bsums[blockIdx.x] = incl;       // block total
}

// finalize with fused block-sums scan
__global__ void finalize_kernel() {
    __shared__ int pref[NB];
    int tid = threadIdx.x;
    if (tid < NB) pref[tid] = g_bsums[tid];
    __syncthreads();
    if (tid == 0) {
        int run = 0;
        #pragma unroll 7
        for (int j = 0; j < NB; ++j) { int t = pref[j]; pref[j] = run; run += t; }
    }
    __syncthreads();
    int i = blockIdx.x * blockDim.x + tid;
    if (i < NN) {
        int off = g_offsets[i] + pref[i >> 10];
        g_offsets[i] = off;
        int c = g_counts[i];
        g_deginv[i]  = 1.0f / (float)((c > 1) ? c : 1);
    }
}

// atomic-free scatter + fused W fp16 preconversion (extra 64 blocks)
#define SC_BLOCKS ((EE + 255) / 256)
__global__ void scatter_fused_kernel(const int* __restrict__ src, const int* __restrict__ dst,
                                     const float* __restrict__ W1s, const float* __restrict__ W1n,
                                     const float* __restrict__ W2s, const float* __restrict__ W2n) {
    if (blockIdx.x < SC_BLOCKS) {
        int i = blockIdx.x * 256 + threadIdx.x;
        if (i < EE) {
            int d = dst[i];
            int p = __ldg(&g_offsets[d]) + g_rank[i];
            g_csr_src[p] = src[i];
        }
    } else {
        int i = (blockIdx.x - SC_BLOCKS) * 256 + threadIdx.x;
        if (i >= 16384) return;
        int layer = i >> 13;
        int r256  = (i >> 5) & 255;
        int c4    = i & 31;
        const float* Wsrc = (layer == 0)
            ? ((r256 < 128) ? W1s + (size_t)r256 * DD : W1n + (size_t)(r256 - 128) * DD)
            : ((r256 < 128) ? W2s + (size_t)r256 * DD : W2n + (size_t)(r256 - 128) * DD);
        float4 v = *reinterpret_cast<const float4*>(Wsrc + c4 * 4);
        __half2 h0 = __floats2half2_rn(v.x, v.y);
        __half2 h1 = __floats2half2_rn(v.z, v.w);
        reinterpret_cast<uint2*>(g_wh)[i] = make_uint2(*(uint32_t*)&h0, *(uint32_t*)&h1);
    }
}

// -------- mean aggregation: warp per node, edge-unroll x8 (frozen structure),
// fp16 gather (uint2/lane), fp32 accumulate, fp16 mean out --------
__global__ void agg_kernel(const __half* __restrict__ x, __half* __restrict__ outmean) {
    int node = (blockIdx.x * blockDim.x + threadIdx.x) >> 5;
    int lane = threadIdx.x & 31;
    if (node >= NN) return;
    int s   = g_offsets[node];
    int cnt = g_counts[node];
    const uint2* xr = reinterpret_cast<const uint2*>(x);
    float a0 = 0.f, a1 = 0.f, a2 = 0.f, a3 = 0.f;
    int t = 0;
    for (; t + 8 <= cnt; t += 8) {
        int idx[8];
        #pragma unroll
        for (int u = 0; u < 8; ++u) idx[u] = __ldg(&g_csr_src[s + t + u]);
        uint2 v[8];
        #pragma unroll
        for (int u = 0; u < 8; ++u)
            v[u] = __ldg(&xr[(size_t)idx[u] * 32 + lane]);
        #pragma unroll
        for (int u = 0; u < 8; ++u) {
            float2 f0 = __half22float2(*reinterpret_cast<__half2*>(&v[u].x));
            float2 f1 = __half22float2(*reinterpret_cast<__half2*>(&v[u].y));
            a0 += f0.x; a1 += f0.y; a2 += f1.x; a3 += f1.y;
        }
    }
    for (; t < cnt; ++t) {
        int i0 = __ldg(&g_csr_src[s + t]);
        uint2 v = __ldg(&xr[(size_t)i0 * 32 + lane]);
        float2 f0 = __half22float2(*reinterpret_cast<__half2*>(&v.x));
        float2 f1 = __half22float2(*reinterpret_cast<__half2*>(&v.y));
        a0 += f0.x; a1 += f0.y; a2 += f1.x; a3 += f1.y;
    }
    float di = g_deginv[node];
    __half2 o0 = __floats2half2_rn(a0 * di, a1 * di);
    __half2 o1 = __floats2half2_rn(a2 * di, a3 * di);
    reinterpret_cast<uint2*>(outmean)[(size_t)node * 32 + lane] =
        make_uint2(*(uint32_t*)&o0, *(uint32_t*)&o1);
}

// ====== fp16 single-product tensor-core GEMM: fp16 A in gmem, double-buffered ======
__device__ __forceinline__ uint32_t smem_u32(const void* p) {
    uint32_t a;
    asm("{ .reg .u64 t; cvta.to.shared.u64 t, %1; cvt.u32.u64 %0, t; }" : "=r"(a) : "l"(p));
    return a;
}
__device__ __forceinline__ void ldsm_x4(uint32_t& r0, uint32_t& r1, uint32_t& r2, uint32_t& r3, uint32_t a) {
    asm volatile("ldmatrix.sync.aligned.m8n8.x4.shared.b16 {%0,%1,%2,%3}, [%4];"
                 : "=r"(r0), "=r"(r1), "=r"(r2), "=r"(r3) : "r"(a));
}
__device__ __forceinline__ void ldsm_x4_t(uint32_t& r0, uint32_t& r1, uint32_t& r2, uint32_t& r3, uint32_t a) {
    asm volatile("ldmatrix.sync.aligned.m8n8.x4.trans.shared.b16 {%0,%1,%2,%3}, [%4];"
                 : "=r"(r0), "=r"(r1), "=r"(r2), "=r"(r3) : "r"(a));
}
__device__ __forceinline__ void mma_fp16(float* c, uint32_t a0, uint32_t a1, uint32_t a2, uint32_t a3,
                                         uint32_t b0, uint32_t b1) {
    asm volatile("mma.sync.aligned.m16n8k16.row.col.f32.f16.f16.f32 "
                 "{%0,%1,%2,%3}, {%4,%5,%6,%7}, {%8,%9}, {%0,%1,%2,%3};"
                 : "+f"(c[0]), "+f"(c[1]), "+f"(c[2]), "+f"(c[3])
                 : "r"(a0), "r"(a1), "r"(a2), "r"(a3), "r"(b0), "r"(b1));
}
__device__ __forceinline__ uint32_t pack_h2(float x, float y) {
    __half2 t = __floats2half2_rn(x, y);
    return *reinterpret_cast<uint32_t*>(&t);
}

#define APAD 40
#define BPAD 136
#define OFF_A 0
#define OFF_B 10240          // 128*APAD*2
#define BUFSZ 18944          // OFF_B + 32*BPAD*2
#define GSMEM (2 * BUFSZ)

// mode 1: relu, write fp16 to outh. mode 0: write fp32 to outf.
__global__ __launch_bounds__(256, 2) void gemm_mma_kernel(
    const __half* __restrict__ A1, const __half* __restrict__ A2,
    const __half* __restrict__ Wh,   // [256 k][128 n] fp16
    const float* __restrict__ bias,
    float* __restrict__ outf, __half* __restrict__ outh, int mode)
{
    extern __shared__ char smem[];
    int tid = threadIdx.x, lane = tid & 31, wid = tid >> 5;
    int warp_m = wid & 3;
    int warp_n = wid >> 2;
    int m0 = blockIdx.x * 128;
    uint32_t sb = smem_u32(smem);

    float acc[2][8][4];
    #pragma unroll
    for (int i = 0; i < 2; ++i)
        #pragma unroll
        for (int j = 0; j < 8; ++j)
            #pragma unroll
            for (int q = 0; q < 4; ++q) acc[i][j][q] = 0.f;

    int a_lrow = lane & 15;
    int a_lcol = (lane >> 4) << 3;
    int b_lk   = lane & 15;
    int b_ln   = (lane >> 4) << 3;

    uint2 av[4];
    // ---- prologue: copy chunk 0 into buffer 0 ----
    #pragma unroll
    for (int i = 0; i < 4; ++i) {
        int f = tid + i * 256;
        int row = f >> 3, c4 = (f & 7) * 4;     // 4 halves per slot
        int gm = m0 + row;
        av[i] = (gm < NN) ? __ldg(reinterpret_cast<const uint2*>(A1 + (size_t)gm * DD + c4))
                          : make_uint2(0u, 0u);
    }
    {
        char* base = smem;
        #pragma unroll
        for (int i = 0; i < 4; ++i) {
            int f = tid + i * 256;
            int row = f >> 3, c4 = (f & 7) * 4;
            *reinterpret_cast<uint2*>(base + OFF_A + (uint32_t)(row * APAD + c4) * 2) = av[i];
        }
        #pragma unroll
        for (int i = 0; i < 2; ++i) {
            int u = tid + i * 256;             // 32 k-rows x 16 uint4-groups
            int kr = u >> 4, n8 = (u & 15) * 8;
            uint4 v = __ldg(reinterpret_cast<const uint4*>(Wh + (size_t)kr * DD + n8));
            *reinterpret_cast<uint4*>(base + OFF_B + (uint32_t)(kr * BPAD + n8) * 2) = v;
        }
    }
    __syncthreads();

    for (int ch = 0; ch < 8; ++ch) {
        // ---- prefetch next chunk's A into registers ----
        uint2 av2[4];
        if (ch < 7) {
            const __half* Abase = (ch + 1 < 4) ? A1 : A2;
            int cb = ((ch + 1) & 3) * 32;
            #pragma unroll
            for (int i = 0; i < 4; ++i) {
                int f = tid + i * 256;
                int row = f >> 3, c4 = (f & 7) * 4;
                int gm = m0 + row;
                av2[i] = (gm < NN) ? __ldg(reinterpret_cast<const uint2*>(Abase + (size_t)gm * DD + cb + c4))
                                   : make_uint2(0u, 0u);
            }
        }

        // ---- compute from buffer ch&1 ----
        uint32_t bufbase = sb + (uint32_t)(ch & 1) * BUFSZ;
        uint32_t a_b = bufbase + OFF_A;
        uint32_t b_b = bufbase + OFF_B;

        #pragma unroll
        for (int ks = 0; ks < 2; ++ks) {
            uint32_t a[2][4];
            #pragma unroll
            for (int mt = 0; mt < 2; ++mt) {
                int row = warp_m * 32 + mt * 16 + a_lrow;
                int col = ks * 16 + a_lcol;
                ldsm_x4(a[mt][0], a[mt][1], a[mt][2], a[mt][3],
                        a_b + (uint32_t)(row * APAD + col) * 2);
            }
            #pragma unroll
            for (int ng = 0; ng < 4; ++ng) {
                int kk = ks * 16 + b_lk;
                int nn = warp_n * 64 + ng * 16 + b_ln;
                uint32_t b0, b1, b2, b3;
                ldsm_x4_t(b0, b1, b2, b3, b_b + (uint32_t)(kk * BPAD + nn) * 2);
                #pragma unroll
                for (int mt = 0; mt < 2; ++mt) {
                    mma_fp16(acc[mt][ng * 2 + 0], a[mt][0], a[mt][1], a[mt][2], a[mt][3], b0, b1);
                    mma_fp16(acc[mt][ng * 2 + 1], a[mt][0], a[mt][1], a[mt][2], a[mt][3], b2, b3);
                }
            }
        }

        // ---- store next chunk into other buffer (pure copies) ----
        if (ch < 7) {
            char* base = smem + ((ch + 1) & 1) * BUFSZ;
            #pragma unroll
            for (int i = 0; i < 4; ++i) {
                int f = tid + i * 256;
                int row = f >> 3, c4 = (f & 7) * 4;
                *reinterpret_cast<uint2*>(base + OFF_A + (uint32_t)(row * APAD + c4) * 2) = av2[i];
            }
            #pragma unroll
            for (int i = 0; i < 2; ++i) {
                int u = tid + i * 256;
                int kr = u >> 4, n8 = (u & 15) * 8;
                uint4 v = __ldg(reinterpret_cast<const uint4*>(Wh + (size_t)((ch + 1) * 32 + kr) * DD + n8));
                *reinterpret_cast<uint4*>(base + OFF_B + (uint32_t)(kr * BPAD + n8) * 2) = v;
            }
            __syncthreads();
        }
    }

    // --- epilogue ---
    int crow = lane >> 2;
    int ccol = (lane & 3) * 2;
    #pragma unroll
    for (int mt = 0; mt < 2; ++mt) {
        #pragma unroll
        for (int nt = 0; nt < 8; ++nt) {
            int col = warp_n * 64 + nt * 8 + ccol;
            float2 bb = __ldg(reinterpret_cast<const float2*>(bias + col));
            #pragma unroll
            for (int h = 0; h < 2; ++h) {
                int row = m0 + warp_m * 32 + mt * 16 + crow + h * 8;
                if (row >= NN) continue;
                float lo = acc[mt][nt][h * 2 + 0] + bb.x;
                float hi = acc[mt][nt][h * 2 + 1] + bb.y;
                if (mode == 1) {
                    lo = fmaxf(lo, 0.f); hi = fmaxf(hi, 0.f);
                    *reinterpret_cast<uint32_t*>(outh + (size_t)row * DD + col) = pack_h2(lo, hi);
                } else {
                    *reinterpret_cast<float2*>(outf + (size_t)row * DD + col) = make_float2(lo, hi);
                }
            }
        }
    }
}

// ---------------- launch ----------------
extern "C" void kernel_launch(void* const* d_in, const int* in_sizes, int n_in,
                              void* d_out, int out_size) {
    const float* in_feat  = (const float*)d_in[0];
    const float* W1_self  = (const float*)d_in[1];
    const float* W1_neigh = (const float*)d_in[2];
    const float* b1       = (const float*)d_in[3];
    const float* W2_self  = (const float*)d_in[4];
    const float* W2_neigh = (const float*)d_in[5];
    const float* b2       = (const float*)d_in[6];
    const int*   src      = (const int*)d_in[7];
    const int*   dst      = (const int*)d_in[8];
    float* out = (float*)d_out;

    int* counts_p;
    __half *xh_p, *mh_p, *hh_p, *wh_p;
    cudaGetSymbolAddress((void**)&counts_p, g_counts);
    cudaGetSymbolAddress((void**)&xh_p, g_xh);
    cudaGetSymbolAddress((void**)&mh_p, g_mh);
    cudaGetSymbolAddress((void**)&hh_p, g_hh);
    cudaGetSymbolAddress((void**)&wh_p, g_wh);

    cudaFuncSetAttribute(gemm_mma_kernel, cudaFuncAttributeMaxDynamicSharedMemorySize, GSMEM);

    cudaMemsetAsync(counts_p, 0, NN * sizeof(int));

    int conv_blocks = (NN * DD / 4 + 255) / 256;
    hist_fused_kernel<<<HB + conv_blocks, 256>>>(dst, in_feat);
    scan_local_kernel<<<NB, 1024>>>();
    finalize_kernel<<<(NN + 255) / 256, 256>>>();
    scatter_fused_kernel<<<SC_BLOCKS + 64, 256>>>(src, dst,
        W1_self, W1_neigh, W2_self, W2_neigh);

    int agg_grid  = (NN + 7) / 8;
    int gemm_grid = (NN + 127) / 128;

    // layer 1
    agg_kernel<<<agg_grid, 256>>>(xh_p, mh_p);
    gemm_mma_kernel<<<gemm_grid, 256, GSMEM>>>(xh_p, mh_p, wh_p, b1, nullptr, hh_p, 1);
    // layer 2
    agg_kernel<<<agg_grid, 256>>>(hh_p, mh_p);
    gemm_mma_kernel<<<gemm_grid, 256, GSMEM>>>(hh_p, mh_p, wh_p + 256 * DD, b2, out, nullptr, 0);
}